// round 16
// baseline (speedup 1.0000x reference)
#include <cuda_runtime.h>
#include <cuda_fp16.h>
#include <cstdint>

#define NQ   2048
#define ND   100000
#define NDP  100096          // 782 * 128
#define NTILE 782
#define DIM  128
#define KSEL 10
#define M32  32              // pool rank target (validated margin)
#define TSEL 48              // tiles kept (>=32 pigeonhole-safe)
#define CAPT 96              // tile buffer cap (ties headroom)
#define MPOOL 64             // pool buffer cap (ties headroom)
#define NSTRIDE 18           // n-tile stride (16 x 18 = 288 CTAs, 1 wave @ occ 2)

// ---------------- scratch (static __device__) ----------------------------------
__device__ float  g_x2w[NDP];                   // ||x||^2 - w  (pad rows = +inf)
__device__ __half g_Ah[NQ * DIM];               // fp16 of (-2 * x_tilde)
__device__ __half g_Xh[(size_t)NDP * DIM];      // fp16 of X (pad rows = 0)
__device__ __half g_s[(size_t)NQ * NDP];        // approx score matrix (fp16)
__device__ __half g_tmin[(size_t)NQ * NTILE];   // per-(row,tile) min score

__device__ __forceinline__ uint32_t smem_u32(const void* p) {
    uint32_t a;
    asm("{ .reg .u64 t; cvta.to.shared.u64 t, %1; cvt.u32.u64 %0, t; }" : "=r"(a) : "l"(p));
    return a;
}
__device__ __forceinline__ void ldsm4(uint32_t* r, uint32_t addr) {
    asm volatile("ldmatrix.sync.aligned.m8n8.x4.shared.b16 {%0,%1,%2,%3}, [%4];"
        : "=r"(r[0]), "=r"(r[1]), "=r"(r[2]), "=r"(r[3]) : "r"(addr));
}
__device__ __forceinline__ void mma16816(float* c, const uint32_t* a, const uint32_t* b) {
    asm volatile("mma.sync.aligned.m16n8k16.row.col.f32.f16.f16.f32 "
        "{%0,%1,%2,%3}, {%4,%5,%6,%7}, {%8,%9}, {%0,%1,%2,%3};"
        : "+f"(c[0]), "+f"(c[1]), "+f"(c[2]), "+f"(c[3])
        : "r"(a[0]), "r"(a[1]), "r"(a[2]), "r"(a[3]), "r"(b[0]), "r"(b[1]));
}
__device__ __forceinline__ uint32_t swzc(uint32_t ck, uint32_t s) {
    return ((ck ^ s) & 7u) | (ck & 8u);
}
__device__ __forceinline__ void cp16(uint32_t dst, const void* src) {
    asm volatile("cp.async.cg.shared.global [%0], [%1], 16;" :: "r"(dst), "l"(src));
}
__device__ __forceinline__ void cp_commit() { asm volatile("cp.async.commit_group;"); }
__device__ __forceinline__ void cp_wait1()  { asm volatile("cp.async.wait_group 1;" ::: "memory"); }
__device__ __forceinline__ void stcs32(void* p, uint32_t v) {
    asm volatile("st.global.cs.b32 [%0], %1;" :: "l"(p), "r"(v));
}
// order-preserving 16-bit key for fp16 (ascending key == ascending value)
__device__ __forceinline__ uint32_t h2key(uint16_t b) {
    return (b & 0x8000u) ? (uint32_t)(0xFFFFu ^ b) : (uint32_t)(b | 0x8000u);
}

// ---------------------------------------------------------------------------
// Kernel 1: norms + fp16 conversion (q scaled by -2, X padded to NDP).
// ---------------------------------------------------------------------------
__global__ void prep_kernel(const float* __restrict__ X,
                            const float* __restrict__ w,
                            const float* __restrict__ q) {
    int gw   = (blockIdx.x * 256 + threadIdx.x) >> 5;
    int lane = threadIdx.x & 31;
    if (gw < NDP) {
        if (gw < ND) {
            float4 v = reinterpret_cast<const float4*>(X + (size_t)gw * DIM)[lane];
            float s = v.x * v.x + v.y * v.y + v.z * v.z + v.w * v.w;
            #pragma unroll
            for (int o = 16; o > 0; o >>= 1) s += __shfl_xor_sync(0xffffffffu, s, o);
            __half2* dh = reinterpret_cast<__half2*>(g_Xh + (size_t)gw * DIM + lane * 4);
            dh[0] = __halves2half2(__float2half_rn(v.x), __float2half_rn(v.y));
            dh[1] = __halves2half2(__float2half_rn(v.z), __float2half_rn(v.w));
            if (lane == 0) g_x2w[gw] = s - w[gw];
        } else {
            __half2 z = __halves2half2(__float2half(0.f), __float2half(0.f));
            __half2* dh = reinterpret_cast<__half2*>(g_Xh + (size_t)gw * DIM + lane * 4);
            dh[0] = z; dh[1] = z;
            if (lane == 0) g_x2w[gw] = __int_as_float(0x7f800000);  // +inf
        }
    } else if (gw < NDP + NQ) {
        int r = gw - NDP;
        float4 v = reinterpret_cast<const float4*>(q + (size_t)r * DIM)[lane];
        __half2* dh = reinterpret_cast<__half2*>(g_Ah + (size_t)r * DIM + lane * 4);
        dh[0] = __halves2half2(__float2half_rn(-2.f * v.x), __float2half_rn(-2.f * v.y));
        dh[1] = __halves2half2(__float2half_rn(-2.f * v.z), __float2half_rn(-2.f * v.w));
    }
}

// ---------------------------------------------------------------------------
// Kernel 2: persistent 1-term HMMA GEMM. Each CTA: one A m-tile staged once,
// loop over n-tiles (stride NSTRIDE) with double-buffered B(+x2w) prefetch.
// Writes g_s (fp16) + g_tmin.
// ---------------------------------------------------------------------------
#define SA    0
#define BUFSZ 33792                    // 32768 B-tile + 1024 (x2w: 512 used)
#define BUF0  32768
#define BUF1  66560
#define SWMIN 100352                   // 128 rows x 4 n-warps x float = 2048
#define SMEM_TOTAL 102400

__device__ __forceinline__ void stage_b(uint32_t bufb, int tile, int t) {
    int n0 = tile * 128;
    #pragma unroll
    for (int i = 0; i < 8; i++) {
        int id = t + 256 * i;
        int row = id >> 4, c = id & 15;
        cp16(bufb + row * 256 + swzc((uint32_t)c, row & 7) * 16,
             reinterpret_cast<const char*>(g_Xh) + (size_t)(n0 + row) * 256 + c * 16);
    }
    if (t < 32)
        cp16(bufb + 32768 + t * 16,
             reinterpret_cast<const char*>(g_x2w) + (size_t)tile * 512 + t * 16);
}

__global__ void __launch_bounds__(256, 2)
gemm_hmma_kernel() {
    extern __shared__ char smem[];
    const uint32_t sb = smem_u32(smem);
    const int t = threadIdx.x, lane = t & 31, wid = t >> 5;
    const int m0 = blockIdx.x * 128;
    const int ny = blockIdx.y;
    const int wm = (wid >> 2) * 64, wn = (wid & 3) * 32;

    // stage A once (group 0, together with B tile0)
    #pragma unroll
    for (int i = 0; i < 8; i++) {
        int id = t + 256 * i;
        int row = id >> 4, c = id & 15;
        cp16(sb + SA + row * 256 + swzc((uint32_t)c, row & 7) * 16,
             reinterpret_cast<const char*>(g_Ah) + (size_t)(m0 + row) * 256 + c * 16);
    }
    stage_b(sb + BUF0, ny, t);
    cp_commit();                        // G0 = A + B(tile0) + x2w0
    stage_b(sb + BUF1, ny + NSTRIDE, t);  // ny + 18 < 782 always
    cp_commit();                        // G1

    uint32_t aOff[4], aS[4];
    #pragma unroll
    for (int mf = 0; mf < 4; mf++) {
        int r = wm + mf * 16 + (lane & 15);
        aOff[mf] = (uint32_t)r * 256; aS[mf] = r & 7;
    }
    uint32_t bOff[2], bS[2];
    #pragma unroll
    for (int p = 0; p < 2; p++) {
        int r = wn + p * 16 + (lane & 7) + ((lane >> 4) << 3);
        bOff[p] = (uint32_t)r * 256; bS[p] = r & 7;
    }
    const uint32_t aHi = (lane >> 4) & 1;
    const uint32_t bHi = (lane >> 3) & 1;
    const int g = lane >> 2, tig = lane & 3;

    const int ntiles = (NTILE - ny + NSTRIDE - 1) / NSTRIDE;
    #pragma unroll 1
    for (int k = 0; k < ntiles; k++) {
        const int tile = ny + k * NSTRIDE;
        const int bufoff = (k & 1) ? BUF1 : BUF0;
        const uint32_t bufb = sb + bufoff;

        cp_wait1();                     // buffer k%2 (group G_k) landed
        __syncthreads();                // + all threads done with prev iter

        float acc[4][4][4];
        #pragma unroll
        for (int mf = 0; mf < 4; mf++)
            #pragma unroll
            for (int nf = 0; nf < 4; nf++)
                #pragma unroll
                for (int e = 0; e < 4; e++) acc[mf][nf][e] = 0.f;

        #pragma unroll
        for (int c8 = 0; c8 < 8; c8++) {
            uint32_t ah[4][4], bh[2][4];
            uint32_t ckA = 2 * c8 + aHi, ckB = 2 * c8 + bHi;
            #pragma unroll
            for (int mf = 0; mf < 4; mf++) ldsm4(ah[mf], sb + SA + aOff[mf] + swzc(ckA, aS[mf]) * 16);
            #pragma unroll
            for (int p = 0; p < 2; p++)    ldsm4(bh[p], bufb + bOff[p] + swzc(ckB, bS[p]) * 16);
            #pragma unroll
            for (int mf = 0; mf < 4; mf++)
                #pragma unroll
                for (int nf = 0; nf < 4; nf++)
                    mma16816(acc[mf][nf], ah[mf], &bh[nf >> 1][(nf & 1) * 2]);
        }

        // epilogue: + x2w (from this buffer), fp16 store, per-row min
        const int n0h = tile * 128;
        float rowmin[4][2];
        #pragma unroll
        for (int mf = 0; mf < 4; mf++) {
            int m = m0 + wm + mf * 16 + g;
            __half2 rm0, rm1;
            #pragma unroll
            for (int nf = 0; nf < 4; nf++) {
                int nl = wn + nf * 8 + tig * 2;
                float2 xw = *reinterpret_cast<const float2*>(smem + bufoff + 32768 + nl * 4);
                __half2 h0 = __floats2half2_rn(acc[mf][nf][0] + xw.x, acc[mf][nf][1] + xw.y);
                __half2 h1 = __floats2half2_rn(acc[mf][nf][2] + xw.x, acc[mf][nf][3] + xw.y);
                stcs32(g_s + (size_t)m * NDP + n0h + nl,       *reinterpret_cast<uint32_t*>(&h0));
                stcs32(g_s + (size_t)(m + 8) * NDP + n0h + nl, *reinterpret_cast<uint32_t*>(&h1));
                if (nf == 0) { rm0 = h0; rm1 = h1; }
                else         { rm0 = __hmin2(rm0, h0); rm1 = __hmin2(rm1, h1); }
            }
            rowmin[mf][0] = __half2float(__hmin(__low2half(rm0), __high2half(rm0)));
            rowmin[mf][1] = __half2float(__hmin(__low2half(rm1), __high2half(rm1)));
        }
        #pragma unroll
        for (int mf = 0; mf < 4; mf++)
            #pragma unroll
            for (int rr = 0; rr < 2; rr++) {
                float mv = rowmin[mf][rr];
                mv = fminf(mv, __shfl_xor_sync(0xffffffffu, mv, 1));
                mv = fminf(mv, __shfl_xor_sync(0xffffffffu, mv, 2));
                rowmin[mf][rr] = mv;
            }
        if (tig == 0) {
            float* swm = reinterpret_cast<float*>(smem + SWMIN);
            #pragma unroll
            for (int mf = 0; mf < 4; mf++)
                #pragma unroll
                for (int rr = 0; rr < 2; rr++)
                    swm[(wm + mf * 16 + g + rr * 8) * 4 + (wid & 3)] = rowmin[mf][rr];
        }
        __syncthreads();                // swm complete; buffer reads complete

        if (t < 128) {
            const float* swm = reinterpret_cast<const float*>(smem + SWMIN) + t * 4;
            float mv = fminf(fminf(swm[0], swm[1]), fminf(swm[2], swm[3]));
            g_tmin[(size_t)(m0 + t) * NTILE + tile] = __float2half_rn(mv);
        }
        // prefetch tile k+2 into the buffer just freed
        int tnext = tile + 2 * NSTRIDE;
        if (tnext < NTILE) stage_b(bufb, tnext, t);
        cp_commit();                    // always commit (empty group ok)
    }
}

// ---------------------------------------------------------------------------
// Kernel 3: FUSED radix-threshold select + exact fp32 rescore (validated R15).
// ---------------------------------------------------------------------------
__global__ void __launch_bounds__(256)
select_kernel(const float* __restrict__ X, const float* __restrict__ q,
              const float* __restrict__ w, float* __restrict__ out) {
    const int b = blockIdx.x;
    const int t = threadIdx.x;
    const int lane = t & 31, wid = t >> 5;
    const float FINF = __int_as_float(0x7f800000);

    __shared__ uint16_t kg[CAPT * 128];    // gathered score keys (24576 B)
    __shared__ int selt[CAPT];
    __shared__ int s_cnt, s_cnt2, s_T1, s_T2;
    __shared__ int wc[8];
    __shared__ float qs[DIM];
    __shared__ float pv[MPOOL];            // pool approx vals (+inf pad)
    __shared__ int   pidx[MPOOL];          // pool indices
    __shared__ float cs[MPOOL];            // d2 - w
    __shared__ float cf[MPOOL];            // w - sqrt(d2)

    const __half* tminrow = g_tmin + (size_t)b * NTILE;

    if (t < DIM) qs[t] = q[(size_t)b * DIM + t];
    if (t < MPOOL) { pv[t] = FINF; pidx[t] = 0; }
    if (t == 0) { s_cnt = 0; s_cnt2 = 0; }

    // ---- phase 1: warp 0 binary-search for T1 (48th smallest tile-min key)
    if (wid == 0) {
        uint32_t k[25];
        #pragma unroll
        for (int i = 0; i < 25; i++) {
            int idx = lane + 32 * i;
            k[i] = (idx < NTILE) ? h2key(__half_as_ushort(tminrow[idx])) : 0xFFFFFFFFu;
        }
        uint32_t lo = 0, hi = 0xFFFFu;
        while (lo < hi) {
            uint32_t mid = (lo + hi) >> 1;
            int c = 0;
            #pragma unroll
            for (int i = 0; i < 25; i++) c += (k[i] <= mid);
            c = __reduce_add_sync(0xffffffffu, c);
            if (c >= TSEL) hi = mid; else lo = mid + 1;
        }
        if (lane == 0) s_T1 = (int)lo;
    }
    __syncthreads();

    // ---- phase 2: compact tile ids with key <= T1
    {
        const uint32_t T1 = (uint32_t)s_T1;
        for (int idx = t; idx < NTILE; idx += 256) {
            if (h2key(__half_as_ushort(tminrow[idx])) <= T1) {
                int pos = atomicAdd(&s_cnt, 1);
                if (pos < CAPT) selt[pos] = idx;
            }
        }
    }
    __syncthreads();
    const int c1 = min(s_cnt, CAPT);
    const int ntot = c1 * 128;

    // ---- phase 3: gather selected tiles' score keys into smem
    {
        const __half* srow = g_s + (size_t)b * NDP;
        for (int g = t; g < ntot; g += 256) {
            int slot = g >> 7, col = g & 127;
            kg[g] = (uint16_t)h2key(__half_as_ushort(srow[selt[slot] * 128 + col]));
        }
    }
    __syncthreads();

    // ---- phase 4: block binary-search for T2 (32nd smallest gathered key)
    {
        uint32_t lo = 0, hi = 0xFFFFu;
        while (lo < hi) {
            uint32_t mid = (lo + hi) >> 1;
            int c = 0;
            for (int g = t; g < ntot; g += 256) c += ((uint32_t)kg[g] <= mid);
            c = __reduce_add_sync(0xffffffffu, c);
            if (lane == 0) wc[wid] = c;
            __syncthreads();
            int tot = 0;
            #pragma unroll
            for (int i = 0; i < 8; i++) tot += wc[i];
            if (tot >= M32) hi = mid; else lo = mid + 1;
            __syncthreads();
        }
        if (t == 0) s_T2 = (int)lo;
    }
    __syncthreads();

    // ---- phase 5: compact pool entries (val, idx) into smem
    {
        const uint32_t T2 = (uint32_t)s_T2;
        for (int g = t; g < ntot; g += 256) {
            uint32_t key = (uint32_t)kg[g];
            if (key <= T2) {
                int pos = atomicAdd(&s_cnt2, 1);
                if (pos < MPOOL) {
                    int slot = g >> 7, col = g & 127;
                    uint16_t hb = (key & 0x8000u) ? (uint16_t)(key ^ 0x8000u)
                                                  : (uint16_t)(0xFFFFu ^ key);
                    pv[pos] = __half2float(__ushort_as_half(hb));
                    pidx[pos] = selt[slot] * 128 + col;
                }
            }
        }
    }
    __syncthreads();

    // ---- phase 6: exact fp32 distances, 8 slots per warp (MLP-batched)
    {
        const float4* q4 = reinterpret_cast<const float4*>(qs);
        float4 qv = q4[lane];
        #pragma unroll
        for (int c = 0; c < MPOOL / 8; c++) {
            int slot = wid * (MPOOL / 8) + c;
            int idx = pidx[slot];
            float4 xv = reinterpret_cast<const float4*>(X + (size_t)idx * DIM)[lane];
            float dx = qv.x - xv.x, dy = qv.y - xv.y, dz = qv.z - xv.z, dw = qv.w - xv.w;
            float d = dx * dx + dy * dy + dz * dz + dw * dw;
            #pragma unroll
            for (int o = 16; o > 0; o >>= 1) d += __shfl_xor_sync(0xffffffffu, d, o);
            if (lane == 0) {
                bool pad = (__float_as_int(pv[slot]) == 0x7f800000);
                float wn = w[idx];
                cs[slot] = pad ? FINF : d - wn;
                cf[slot] = pad ? -FINF : wn - sqrtf(fmaxf(d, 0.0f));
            }
        }
    }
    __syncthreads();

    // ---- phase 7: warp 0 extracts top-10 by cs, tracks argmax cf
    if (wid == 0) {
        float c0 = cs[lane], c1 = cs[lane + 32];
        float bestf = -FINF; int besti = 0;
        #pragma unroll
        for (int r = 0; r < KSEL; r++) {
            float v; int id;
            if (c0 <= c1) { v = c0; id = lane; } else { v = c1; id = lane + 32; }
            #pragma unroll
            for (int o = 16; o > 0; o >>= 1) {
                float ov = __shfl_xor_sync(0xffffffffu, v, o);
                int   oi = __shfl_xor_sync(0xffffffffu, id, o);
                if (ov < v || (ov == v && oi < id)) { v = ov; id = oi; }
            }
            float f = cf[id];
            if (f > bestf) { bestf = f; besti = pidx[id]; }
            if (id == lane) c0 = FINF;
            else if (id == lane + 32) c1 = FINF;
        }
        if (lane == 0) {
            out[b]      = bestf;
            out[NQ + b] = (float)besti;
        }
    }
}

extern "C" void kernel_launch(void* const* d_in, const int* in_sizes, int n_in,
                              void* d_out, int out_size) {
    const float* q = (const float*)d_in[0];   // x_tilde [2048,128]
    const float* X = (const float*)d_in[1];   // X [100000,128]
    const float* w = (const float*)d_in[2];   // w [100000,1]
    float* out = (float*)d_out;

    cudaFuncSetAttribute(gemm_hmma_kernel,
                         cudaFuncAttributeMaxDynamicSharedMemorySize, SMEM_TOTAL);

    prep_kernel<<<(NDP + NQ) / 8, 256>>>(X, w, q);
    dim3 g(NQ / 128, NSTRIDE);                // (16, 18) = 288 CTAs, one wave
    gemm_hmma_kernel<<<g, 256, SMEM_TOTAL>>>();
    select_kernel<<<NQ, 256>>>(X, q, w, out);
}

// round 17
// speedup vs baseline: 1.0526x; 1.0526x over previous
#include <cuda_runtime.h>
#include <cuda_fp16.h>
#include <cstdint>

#define NQ   2048
#define ND   100000
#define NDP  100096          // 782 * 128
#define NTILE 782
#define DIM  128
#define KSEL 10
#define M32  32              // pool rank target (validated margin)
#define TSEL 48              // tiles kept (>=32 pigeonhole-safe)
#define CAPT 96              // tile buffer cap (ties headroom)
#define MPOOL 64             // pool buffer cap (ties headroom)

// ---------------- scratch (static __device__) ----------------------------------
__device__ float  g_x2w[NDP];                   // ||x||^2 - w  (pad rows = +inf)
__device__ __half g_Ah[NQ * DIM];               // fp16 of (-2 * x_tilde)
__device__ __half g_Xh[(size_t)NDP * DIM];      // fp16 of X (pad rows = 0)
__device__ __half g_s[(size_t)NQ * NDP];        // approx score matrix (fp16)
__device__ __half g_tmin[(size_t)NQ * NTILE];   // per-(row,tile) min score

__device__ __forceinline__ uint32_t smem_u32(const void* p) {
    uint32_t a;
    asm("{ .reg .u64 t; cvta.to.shared.u64 t, %1; cvt.u32.u64 %0, t; }" : "=r"(a) : "l"(p));
    return a;
}
__device__ __forceinline__ void ldsm4(uint32_t* r, uint32_t addr) {
    asm volatile("ldmatrix.sync.aligned.m8n8.x4.shared.b16 {%0,%1,%2,%3}, [%4];"
        : "=r"(r[0]), "=r"(r[1]), "=r"(r[2]), "=r"(r[3]) : "r"(addr));
}
__device__ __forceinline__ void mma16816(float* c, const uint32_t* a, const uint32_t* b) {
    asm volatile("mma.sync.aligned.m16n8k16.row.col.f32.f16.f16.f32 "
        "{%0,%1,%2,%3}, {%4,%5,%6,%7}, {%8,%9}, {%0,%1,%2,%3};"
        : "+f"(c[0]), "+f"(c[1]), "+f"(c[2]), "+f"(c[3])
        : "r"(a[0]), "r"(a[1]), "r"(a[2]), "r"(a[3]), "r"(b[0]), "r"(b[1]));
}
__device__ __forceinline__ uint32_t swzc(uint32_t ck, uint32_t s) {
    return ((ck ^ s) & 7u) | (ck & 8u);
}
__device__ __forceinline__ void cp16(uint32_t dst, const void* src) {
    asm volatile("cp.async.cg.shared.global [%0], [%1], 16;" :: "r"(dst), "l"(src));
}
__device__ __forceinline__ void cp_commit() { asm volatile("cp.async.commit_group;"); }
__device__ __forceinline__ void cp_wait1()  { asm volatile("cp.async.wait_group 1;" ::: "memory"); }
__device__ __forceinline__ void cp_wait0()  { asm volatile("cp.async.wait_group 0;" ::: "memory"); }
__device__ __forceinline__ void stcs32(void* p, uint32_t v) {
    asm volatile("st.global.cs.b32 [%0], %1;" :: "l"(p), "r"(v));
}
// order-preserving 16-bit key for fp16 (ascending key == ascending value)
__device__ __forceinline__ uint32_t h2key(uint16_t b) {
    return (b & 0x8000u) ? (uint32_t)(0xFFFFu ^ b) : (uint32_t)(b | 0x8000u);
}

// ---------------------------------------------------------------------------
// Kernel 1: norms + fp16 conversion (q scaled by -2, X padded to NDP).
// ---------------------------------------------------------------------------
__global__ void prep_kernel(const float* __restrict__ X,
                            const float* __restrict__ w,
                            const float* __restrict__ q) {
    int gw   = (blockIdx.x * 256 + threadIdx.x) >> 5;
    int lane = threadIdx.x & 31;
    if (gw < NDP) {
        if (gw < ND) {
            float4 v = reinterpret_cast<const float4*>(X + (size_t)gw * DIM)[lane];
            float s = v.x * v.x + v.y * v.y + v.z * v.z + v.w * v.w;
            #pragma unroll
            for (int o = 16; o > 0; o >>= 1) s += __shfl_xor_sync(0xffffffffu, s, o);
            __half2* dh = reinterpret_cast<__half2*>(g_Xh + (size_t)gw * DIM + lane * 4);
            dh[0] = __halves2half2(__float2half_rn(v.x), __float2half_rn(v.y));
            dh[1] = __halves2half2(__float2half_rn(v.z), __float2half_rn(v.w));
            if (lane == 0) g_x2w[gw] = s - w[gw];
        } else {
            __half2 z = __halves2half2(__float2half(0.f), __float2half(0.f));
            __half2* dh = reinterpret_cast<__half2*>(g_Xh + (size_t)gw * DIM + lane * 4);
            dh[0] = z; dh[1] = z;
            if (lane == 0) g_x2w[gw] = __int_as_float(0x7f800000);  // +inf
        }
    } else if (gw < NDP + NQ) {
        int r = gw - NDP;
        float4 v = reinterpret_cast<const float4*>(q + (size_t)r * DIM)[lane];
        __half2* dh = reinterpret_cast<__half2*>(g_Ah + (size_t)r * DIM + lane * 4);
        dh[0] = __halves2half2(__float2half_rn(-2.f * v.x), __float2half_rn(-2.f * v.y));
        dh[1] = __halves2half2(__float2half_rn(-2.f * v.z), __float2half_rn(-2.f * v.w));
    }
}

// ---------------------------------------------------------------------------
// Kernel 2: 1-term HMMA GEMM, TWO n-tiles per CTA -> g_s (fp16) + g_tmin.
// (validated R14/R15 version, reverted from persistent)
// ---------------------------------------------------------------------------
#define SA_H 0
#define SB0  32768
#define SB1  65536
#define SX2  98304                     // 2 x 128 floats = 1024
#define SWMIN 99328                    // 2 x 2048
#define SMEM_TOTAL 103424

__global__ void __launch_bounds__(256, 2)
gemm_hmma_kernel() {
    extern __shared__ char smem[];
    const uint32_t sb = smem_u32(smem);
    const int t = threadIdx.x, lane = t & 31, wid = t >> 5;
    const int m0 = blockIdx.x * 128, n0 = blockIdx.y * 256;
    const int wm = (wid >> 2) * 64, wn = (wid & 3) * 32;

    reinterpret_cast<float*>(smem + SX2)[t] = g_x2w[n0 + t];

    #pragma unroll
    for (int i = 0; i < 16; i++) {
        int id = t + 256 * i;
        int tile = id >> 11;            // 0=Ah 1=B0
        int within = id & 2047;
        int row = within >> 4, c = within & 15;
        const __half* src = tile ? g_Xh : g_Ah;
        int grow = (tile ? n0 : m0) + row;
        uint32_t dst = sb + (tile ? SB0 : SA_H) + row * 256 + swzc((uint32_t)c, row & 7) * 16;
        cp16(dst, reinterpret_cast<const char*>(src) + (size_t)grow * 256 + c * 16);
    }
    cp_commit();
    #pragma unroll
    for (int i = 0; i < 8; i++) {
        int id = t + 256 * i;
        int row = id >> 4, c = id & 15;
        uint32_t dst = sb + SB1 + row * 256 + swzc((uint32_t)c, row & 7) * 16;
        cp16(dst, reinterpret_cast<const char*>(g_Xh) + (size_t)(n0 + 128 + row) * 256 + c * 16);
    }
    cp_commit();

    uint32_t aOff[4], aS[4];
    #pragma unroll
    for (int mf = 0; mf < 4; mf++) {
        int r = wm + mf * 16 + (lane & 15);
        aOff[mf] = (uint32_t)r * 256; aS[mf] = r & 7;
    }
    uint32_t bOff[2], bS[2];
    #pragma unroll
    for (int p = 0; p < 2; p++) {
        int r = wn + p * 16 + (lane & 7) + ((lane >> 4) << 3);
        bOff[p] = (uint32_t)r * 256; bS[p] = r & 7;
    }
    const uint32_t aHi = (lane >> 4) & 1;
    const uint32_t bHi = (lane >> 3) & 1;
    const int g = lane >> 2, tig = lane & 3;

    #pragma unroll 1
    for (int half = 0; half < 2; half++) {
        if (half == 0) cp_wait1(); else cp_wait0();
        __syncthreads();
        const uint32_t sbb = sb + (half ? SB1 : SB0);
        const int n0h = n0 + half * 128;

        float acc[4][4][4];
        #pragma unroll
        for (int mf = 0; mf < 4; mf++)
            #pragma unroll
            for (int nf = 0; nf < 4; nf++)
                #pragma unroll
                for (int e = 0; e < 4; e++) acc[mf][nf][e] = 0.f;

        #pragma unroll
        for (int c8 = 0; c8 < 8; c8++) {
            uint32_t ah[4][4], bh[2][4];
            uint32_t ckA = 2 * c8 + aHi, ckB = 2 * c8 + bHi;
            #pragma unroll
            for (int mf = 0; mf < 4; mf++) ldsm4(ah[mf], sb + SA_H + aOff[mf] + swzc(ckA, aS[mf]) * 16);
            #pragma unroll
            for (int p = 0; p < 2; p++)    ldsm4(bh[p], sbb + bOff[p] + swzc(ckB, bS[p]) * 16);
            #pragma unroll
            for (int mf = 0; mf < 4; mf++)
                #pragma unroll
                for (int nf = 0; nf < 4; nf++)
                    mma16816(acc[mf][nf], ah[mf], &bh[nf >> 1][(nf & 1) * 2]);
        }

        float rowmin[4][2];
        #pragma unroll
        for (int mf = 0; mf < 4; mf++) {
            int m = m0 + wm + mf * 16 + g;
            __half2 rm0, rm1;
            #pragma unroll
            for (int nf = 0; nf < 4; nf++) {
                int nl = wn + nf * 8 + tig * 2;
                float2 xw = *reinterpret_cast<const float2*>(smem + SX2 + half * 512 + nl * 4);
                __half2 h0 = __floats2half2_rn(acc[mf][nf][0] + xw.x, acc[mf][nf][1] + xw.y);
                __half2 h1 = __floats2half2_rn(acc[mf][nf][2] + xw.x, acc[mf][nf][3] + xw.y);
                stcs32(g_s + (size_t)m * NDP + n0h + nl,       *reinterpret_cast<uint32_t*>(&h0));
                stcs32(g_s + (size_t)(m + 8) * NDP + n0h + nl, *reinterpret_cast<uint32_t*>(&h1));
                if (nf == 0) { rm0 = h0; rm1 = h1; }
                else         { rm0 = __hmin2(rm0, h0); rm1 = __hmin2(rm1, h1); }
            }
            rowmin[mf][0] = __half2float(__hmin(__low2half(rm0), __high2half(rm0)));
            rowmin[mf][1] = __half2float(__hmin(__low2half(rm1), __high2half(rm1)));
        }
        #pragma unroll
        for (int mf = 0; mf < 4; mf++)
            #pragma unroll
            for (int rr = 0; rr < 2; rr++) {
                float mv = rowmin[mf][rr];
                mv = fminf(mv, __shfl_xor_sync(0xffffffffu, mv, 1));
                mv = fminf(mv, __shfl_xor_sync(0xffffffffu, mv, 2));
                rowmin[mf][rr] = mv;
            }
        if (tig == 0) {
            float* swm = reinterpret_cast<float*>(smem + SWMIN + half * 2048);
            #pragma unroll
            for (int mf = 0; mf < 4; mf++)
                #pragma unroll
                for (int rr = 0; rr < 2; rr++)
                    swm[(wm + mf * 16 + g + rr * 8) * 4 + (wid & 3)] = rowmin[mf][rr];
        }
    }
    __syncthreads();
    if (t < 128) {
        #pragma unroll
        for (int half = 0; half < 2; half++) {
            const float* swm = reinterpret_cast<const float*>(smem + SWMIN + half * 2048) + t * 4;
            float mv = fminf(fminf(swm[0], swm[1]), fminf(swm[2], swm[3]));
            g_tmin[(size_t)(m0 + t) * NTILE + blockIdx.y * 2 + half] = __float2half_rn(mv);
        }
    }
}

// ---------------------------------------------------------------------------
// Kernel 3: FUSED radix-threshold select + exact fp32 rescore -> outputs.
// Phase 6 now MLP-batched: all pidx/w loads hoisted, X rows in groups of 4.
// ---------------------------------------------------------------------------
__global__ void __launch_bounds__(256)
select_kernel(const float* __restrict__ X, const float* __restrict__ q,
              const float* __restrict__ w, float* __restrict__ out) {
    const int b = blockIdx.x;
    const int t = threadIdx.x;
    const int lane = t & 31, wid = t >> 5;
    const float FINF = __int_as_float(0x7f800000);

    __shared__ uint16_t kg[CAPT * 128];    // gathered score keys (24576 B)
    __shared__ int selt[CAPT];
    __shared__ int s_cnt, s_cnt2, s_T1, s_T2;
    __shared__ int wc[8];
    __shared__ float qs[DIM];
    __shared__ float pv[MPOOL];            // pool approx vals (+inf pad)
    __shared__ int   pidx[MPOOL];          // pool indices
    __shared__ float cs[MPOOL];            // d2 - w
    __shared__ float cf[MPOOL];            // w - sqrt(d2)

    const __half* tminrow = g_tmin + (size_t)b * NTILE;

    if (t < DIM) qs[t] = q[(size_t)b * DIM + t];
    if (t < MPOOL) { pv[t] = FINF; pidx[t] = 0; }
    if (t == 0) { s_cnt = 0; s_cnt2 = 0; }

    // ---- phase 1: warp 0 binary-search for T1 (48th smallest tile-min key)
    if (wid == 0) {
        uint32_t k[25];
        #pragma unroll
        for (int i = 0; i < 25; i++) {
            int idx = lane + 32 * i;
            k[i] = (idx < NTILE) ? h2key(__half_as_ushort(tminrow[idx])) : 0xFFFFFFFFu;
        }
        uint32_t lo = 0, hi = 0xFFFFu;
        while (lo < hi) {
            uint32_t mid = (lo + hi) >> 1;
            int c = 0;
            #pragma unroll
            for (int i = 0; i < 25; i++) c += (k[i] <= mid);
            c = __reduce_add_sync(0xffffffffu, c);
            if (c >= TSEL) hi = mid; else lo = mid + 1;
        }
        if (lane == 0) s_T1 = (int)lo;
    }
    __syncthreads();

    // ---- phase 2: compact tile ids with key <= T1
    {
        const uint32_t T1 = (uint32_t)s_T1;
        for (int idx = t; idx < NTILE; idx += 256) {
            if (h2key(__half_as_ushort(tminrow[idx])) <= T1) {
                int pos = atomicAdd(&s_cnt, 1);
                if (pos < CAPT) selt[pos] = idx;
            }
        }
    }
    __syncthreads();
    const int c1 = min(s_cnt, CAPT);
    const int ntot = c1 * 128;

    // ---- phase 3: gather selected tiles' score keys into smem
    {
        const __half* srow = g_s + (size_t)b * NDP;
        for (int g = t; g < ntot; g += 256) {
            int slot = g >> 7, col = g & 127;
            kg[g] = (uint16_t)h2key(__half_as_ushort(srow[selt[slot] * 128 + col]));
        }
    }
    __syncthreads();

    // ---- phase 4: block binary-search for T2 (32nd smallest gathered key)
    {
        uint32_t lo = 0, hi = 0xFFFFu;
        while (lo < hi) {
            uint32_t mid = (lo + hi) >> 1;
            int c = 0;
            for (int g = t; g < ntot; g += 256) c += ((uint32_t)kg[g] <= mid);
            c = __reduce_add_sync(0xffffffffu, c);
            if (lane == 0) wc[wid] = c;
            __syncthreads();
            int tot = 0;
            #pragma unroll
            for (int i = 0; i < 8; i++) tot += wc[i];
            if (tot >= M32) hi = mid; else lo = mid + 1;
            __syncthreads();
        }
        if (t == 0) s_T2 = (int)lo;
    }
    __syncthreads();

    // ---- phase 5: compact pool entries (val, idx) into smem
    {
        const uint32_t T2 = (uint32_t)s_T2;
        for (int g = t; g < ntot; g += 256) {
            uint32_t key = (uint32_t)kg[g];
            if (key <= T2) {
                int pos = atomicAdd(&s_cnt2, 1);
                if (pos < MPOOL) {
                    int slot = g >> 7, col = g & 127;
                    uint16_t hb = (key & 0x8000u) ? (uint16_t)(key ^ 0x8000u)
                                                  : (uint16_t)(0xFFFFu ^ key);
                    pv[pos] = __half2float(__ushort_as_half(hb));
                    pidx[pos] = selt[slot] * 128 + col;
                }
            }
        }
    }
    __syncthreads();

    // ---- phase 6: exact fp32 distances, MLP-batched (8 slots per warp).
    //      All pidx + w loads hoisted; X rows loaded in 2 groups of 4.
    {
        const float4* q4 = reinterpret_cast<const float4*>(qs);
        const float4* X4 = reinterpret_cast<const float4*>(X);
        float4 qv = q4[lane];
        int idxr[8]; float wr[8];
        #pragma unroll
        for (int c = 0; c < 8; c++) idxr[c] = pidx[wid * 8 + c];
        #pragma unroll
        for (int c = 0; c < 8; c++) wr[c] = __ldg(&w[idxr[c]]);   // broadcast, batched
        #pragma unroll
        for (int gbase = 0; gbase < 8; gbase += 4) {
            float4 xv[4];
            #pragma unroll
            for (int c = 0; c < 4; c++)                            // 4 independent LDG.128
                xv[c] = X4[(size_t)idxr[gbase + c] * 32 + lane];
            #pragma unroll
            for (int c = 0; c < 4; c++) {
                int slot = wid * 8 + gbase + c;
                float dx = qv.x - xv[c].x, dy = qv.y - xv[c].y;
                float dz = qv.z - xv[c].z, dw = qv.w - xv[c].w;
                float d = dx * dx + dy * dy + dz * dz + dw * dw;
                #pragma unroll
                for (int o = 16; o > 0; o >>= 1) d += __shfl_xor_sync(0xffffffffu, d, o);
                if (lane == 0) {
                    bool pad = (__float_as_int(pv[slot]) == 0x7f800000);
                    float wn = wr[gbase + c];
                    cs[slot] = pad ? FINF : d - wn;
                    cf[slot] = pad ? -FINF : wn - sqrtf(fmaxf(d, 0.0f));
                }
            }
        }
    }
    __syncthreads();

    // ---- phase 7: warp 0 extracts top-10 by cs, tracks argmax cf
    if (wid == 0) {
        float c0 = cs[lane], c1 = cs[lane + 32];
        float bestf = -FINF; int besti = 0;
        #pragma unroll
        for (int r = 0; r < KSEL; r++) {
            float v; int id;
            if (c0 <= c1) { v = c0; id = lane; } else { v = c1; id = lane + 32; }
            #pragma unroll
            for (int o = 16; o > 0; o >>= 1) {
                float ov = __shfl_xor_sync(0xffffffffu, v, o);
                int   oi = __shfl_xor_sync(0xffffffffu, id, o);
                if (ov < v || (ov == v && oi < id)) { v = ov; id = oi; }
            }
            float f = cf[id];
            if (f > bestf) { bestf = f; besti = pidx[id]; }
            if (id == lane) c0 = FINF;
            else if (id == lane + 32) c1 = FINF;
        }
        if (lane == 0) {
            out[b]      = bestf;
            out[NQ + b] = (float)besti;
        }
    }
}

extern "C" void kernel_launch(void* const* d_in, const int* in_sizes, int n_in,
                              void* d_out, int out_size) {
    const float* q = (const float*)d_in[0];   // x_tilde [2048,128]
    const float* X = (const float*)d_in[1];   // X [100000,128]
    const float* w = (const float*)d_in[2];   // w [100000,1]
    float* out = (float*)d_out;

    cudaFuncSetAttribute(gemm_hmma_kernel,
                         cudaFuncAttributeMaxDynamicSharedMemorySize, SMEM_TOTAL);

    prep_kernel<<<(NDP + NQ) / 8, 256>>>(X, w, q);
    dim3 g(NQ / 128, NTILE / 2);              // (16, 391): 2 n-tiles per CTA
    gemm_hmma_kernel<<<g, 256, SMEM_TOTAL>>>();
    select_kernel<<<NQ, 256>>>(X, q, w, out);
}